// round 15
// baseline (speedup 1.0000x reference)
#include <cuda_runtime.h>
#include <cuda_bf16.h>
#include <cstdint>

#define NPTS 6912
#define CF 16
#define BB 2
#define TILE 128
#define NT (NPTS / TILE)     /* 54 */
#define JCHUNK 6
#define NJB (NT / JCHUNK)    /* 9 */
#define PREPB (NPTS / 256)   /* 27 */
#define EPSF 1e-8f
#define NEG_SCALE (-14.426950408889634f)
#define POS2SCALE (28.853900817779268f)
#define ROWP 24              /* bf16/row: 16 used + 8 pad -> 48B stride */

typedef unsigned long long u64;

/* ------------------------- packed per-tile records ----------------------- */
struct APack {               /* 16384 B */
    __nv_bfloat16 A[2][TILE][ROWP];     /* hi/lo split, 12KB */
    float X1i[TILE][8];                 /* {Px,Px,Py,Py,Pz,Pz,as,as} 4KB */
};
struct JPack {               /* 16384 B */
    __nv_bfloat16 B[2][TILE][ROWP];     /* 12KB */
    float JT[3][TILE];
    float JN[3][TILE];
    float bt[TILE], bn[TILE];
};

__device__ APack g_ap[BB][NT];
__device__ JPack g_jp[BB][NT];
__device__ float  g_part[BB][PREPB][3];
__device__ double g_S[BB];

/* ------------------------- helpers -------------------------------------- */
__device__ __forceinline__ float2 unpk(u64 v) {
    float2 r; asm("mov.b64 {%0, %1}, %2;" : "=f"(r.x), "=f"(r.y) : "l"(v)); return r;
}
__device__ __forceinline__ void fma2(u64 &d, u64 a, u64 b) {
    asm("fma.rn.f32x2 %0, %1, %2, %0;" : "+l"(d) : "l"(a), "l"(b));
}
__device__ __forceinline__ u64 add2(u64 a, u64 b) {
    u64 r; asm("add.rn.f32x2 %0, %1, %2;" : "=l"(r) : "l"(a), "l"(b)); return r;
}
__device__ __forceinline__ float fexp2(float x) {
    float r; asm("ex2.approx.f32 %0, %1;" : "=f"(r) : "f"(x)); return r;
}
__device__ __forceinline__ uint32_t s2u(const void* p) {
    uint32_t a;
    asm("{ .reg .u64 t; cvta.to.shared.u64 t, %1; cvt.u32.u64 %0, t; }" : "=r"(a) : "l"(p));
    return a;
}
__device__ __forceinline__ void ldsm4(uint32_t r[4], uint32_t addr) {
    asm volatile("ldmatrix.sync.aligned.m8n8.x4.shared.b16 {%0,%1,%2,%3}, [%4];"
                 : "=r"(r[0]), "=r"(r[1]), "=r"(r[2]), "=r"(r[3]) : "r"(addr));
}
__device__ __forceinline__ void mma_bf16(float d[4], const uint32_t a[4],
                                         uint32_t b0, uint32_t b1) {
    asm volatile("mma.sync.aligned.m16n8k16.row.col.f32.bf16.bf16.f32 "
                 "{%0,%1,%2,%3}, {%4,%5,%6,%7}, {%8,%9}, {%0,%1,%2,%3};"
                 : "+f"(d[0]), "+f"(d[1]), "+f"(d[2]), "+f"(d[3])
                 : "r"(a[0]), "r"(a[1]), "r"(a[2]), "r"(a[3]), "r"(b0), "r"(b1));
}
__device__ __forceinline__ void cpa16(uint32_t dst, const void* src) {
    asm volatile("cp.async.cg.shared.global [%0], [%1], 16;" :: "r"(dst), "l"(src));
}
#define CPA_COMMIT() asm volatile("cp.async.commit_group;" ::: "memory")
#define CPA_WAIT0()  asm volatile("cp.async.wait_group 0;" ::: "memory")

/* ------------------------- prep ----------------------------------------- */
__global__ void prep_kernel(const float* __restrict__ f1, const float* __restrict__ f2,
                            const float* __restrict__ dp1, const float* __restrict__ dp2,
                            const float* __restrict__ pose, const float* __restrict__ yz1) {
    const int b = blockIdx.y;
    const int i = blockIdx.x * blockDim.x + threadIdx.x;
    const int tile = i >> 7, row = i & 127;
    float fns, m1c, m2c;
    {
        float d1 = dp1[b * NPTS + i], d2 = dp2[b * NPTS + i];
        float m1 = (d1 > 0.f) ? 1.f : 0.f;
        float m2 = (d2 > 0.f) ? 1.f : 0.f;
        float v1[CF], v2[CF];
        float s1 = 0.f, s2 = 0.f;
#pragma unroll
        for (int c = 0; c < CF; c++) {
            v1[c] = f1[((size_t)b * CF + c) * NPTS + i];
            v2[c] = f2[((size_t)b * CF + c) * NPTS + i];
            s1 = fmaf(v1[c], v1[c], s1);
            s2 = fmaf(v2[c], v2[c], s2);
        }
        float n1 = sqrtf(s1), n2 = sqrtf(s2);
        float iv1 = m1 / (n1 + EPSF), iv2 = m2 / (n2 + EPSF);

        union { uint4 q[2]; __nv_bfloat162 h[8]; } AH, AL, BH, BL;
#pragma unroll
        for (int t = 0; t < 8; t++) {
            float a0 = v1[2 * t] * iv1,     a1 = v1[2 * t + 1] * iv1;
            __nv_bfloat16 h0 = __float2bfloat16(a0), h1 = __float2bfloat16(a1);
            AH.h[t].x = h0; AH.h[t].y = h1;
            AL.h[t].x = __float2bfloat16(a0 - __bfloat162float(h0));
            AL.h[t].y = __float2bfloat16(a1 - __bfloat162float(h1));
            float b0 = v2[2 * t] * iv2,     b1 = v2[2 * t + 1] * iv2;
            __nv_bfloat16 g0 = __float2bfloat16(b0), g1 = __float2bfloat16(b1);
            BH.h[t].x = g0; BH.h[t].y = g1;
            BL.h[t].x = __float2bfloat16(b0 - __bfloat162float(g0));
            BL.h[t].y = __float2bfloat16(b1 - __bfloat162float(g1));
        }
        APack& ap = g_ap[b][tile];
        JPack& jp = g_jp[b][tile];
        *(uint4*)&ap.A[0][row][0] = AH.q[0];
        *(uint4*)&ap.A[0][row][8] = AH.q[1];
        *(uint4*)&ap.A[1][row][0] = AL.q[0];
        *(uint4*)&ap.A[1][row][8] = AL.q[1];
        *(uint4*)&jp.B[0][row][0] = BH.q[0];
        *(uint4*)&jp.B[0][row][8] = BH.q[1];
        *(uint4*)&jp.B[1][row][0] = BL.q[0];
        *(uint4*)&jp.B[1][row][8] = BL.q[1];

        float y0 = yz1[i], y1 = yz1[NPTS + i], y2 = yz1[2 * NPTS + i];
        float ax = y0 * d1, ay = y1 * d1, az = y2 * d1;
        float as = NEG_SCALE * (ax * ax + ay * ay + az * az);
        *(float4*)&ap.X1i[row][0] = make_float4(POS2SCALE * ax, POS2SCALE * ax,
                                                POS2SCALE * ay, POS2SCALE * ay);
        *(float4*)&ap.X1i[row][4] = make_float4(POS2SCALE * az, POS2SCALE * az, as, as);

        float bx = y0 * d2, by = y1 * d2, bz = y2 * d2;
        jp.JN[0][row] = bx; jp.JN[1][row] = by; jp.JN[2][row] = bz;
        jp.bn[row] = NEG_SCALE * (bx * bx + by * by + bz * bz);
        const float* P = pose + b * 16;
        float tx = P[0] * bx + P[1] * by + P[2]  * bz + P[3];
        float ty = P[4] * bx + P[5] * by + P[6]  * bz + P[7];
        float tz = P[8] * bx + P[9] * by + P[10] * bz + P[11];
        jp.JT[0][row] = tx; jp.JT[1][row] = ty; jp.JT[2][row] = tz;
        jp.bt[row] = NEG_SCALE * (tx * tx + ty * ty + tz * tz);
        fns = n1 * m1 + n2 * m2; m1c = m1; m2c = m2;
    }
#pragma unroll
    for (int o = 16; o; o >>= 1) {
        fns += __shfl_down_sync(0xffffffffu, fns, o);
        m1c += __shfl_down_sync(0xffffffffu, m1c, o);
        m2c += __shfl_down_sync(0xffffffffu, m2c, o);
    }
    __shared__ float rf[8], r1[8], r2[8];
    int w = threadIdx.x >> 5, l = threadIdx.x & 31;
    if (l == 0) { rf[w] = fns; r1[w] = m1c; r2[w] = m2c; }
    __syncthreads();
    if (threadIdx.x == 0) {
        float a = 0.f, c1 = 0.f, c2 = 0.f;
#pragma unroll
        for (int k = 0; k < 8; k++) { a += rf[k]; c1 += r1[k]; c2 += r2[k]; }
        g_part[b][blockIdx.x][0] = a;
        g_part[b][blockIdx.x][1] = c1;
        g_part[b][blockIdx.x][2] = c2;
        if (blockIdx.x == 0) g_S[b] = 0.0;
    }
}

/* --------- pair: 64-row half-strip, 256 threads, 3 blocks/SM ------------ */
struct SmemT {
    __nv_bfloat16 A[2][64][ROWP];       /* 6KB (contig 384 float4) */
    float X1i[64][8];                   /* 2KB (contig 128 float4) */
    JPack jb[2];                        /* 32KB double buffer */
    float warpsum[8];
};

__global__ void __launch_bounds__(256, 3) pair_kernel() {
    __shared__ SmemT sm;
    const int b     = blockIdx.z;
    const int ti    = blockIdx.y >> 1;
    const int ihalf = blockIdx.y & 1;
    const int jbase = blockIdx.x * JCHUNK;
    const int tid = threadIdx.x;
    const int w = tid >> 5, lane = tid & 31;
    const int wy = w >> 2, wx = w & 3;       /* 2x4 warps of 32x32 slabs */

    /* prologue: async-fill A-half (3 contig chunks) + first J-pack */
    {
        const char* gA = (const char*)&g_ap[b][ti];
        float4* sa = (float4*)&sm;           /* A then X1i, contiguous 512 f4 */
#pragma unroll
        for (int k = 0; k < 2; k++) {
            int idx = tid + k * 256;
            const char* src;
            if (idx < 192)      src = gA + (size_t)ihalf * 3072 + (size_t)idx * 16;
            else if (idx < 384) src = gA + 6144 + (size_t)ihalf * 3072 + (size_t)(idx - 192) * 16;
            else                src = gA + 12288 + (size_t)ihalf * 2048 + (size_t)(idx - 384) * 16;
            cpa16(s2u(sa + idx), src);
        }
        const float4* gj = (const float4*)&g_jp[b][jbase];
        float4* sj = (float4*)&sm.jb[0];
#pragma unroll
        for (int k = 0; k < 4; k++)
            cpa16(s2u(sj + tid + k * 256), gj + tid + k * 256);
        CPA_COMMIT();
        CPA_WAIT0();
    }
    __syncthreads();

    /* A fragments + i-geometry: pinned in registers for the whole strip */
    uint32_t af[2][2][4];                     /* [mi][split][4] */
#pragma unroll
    for (int mi = 0; mi < 2; mi++)
#pragma unroll
        for (int s = 0; s < 2; s++) {
            int row = wy * 32 + mi * 16 + (lane & 15);
            int kh  = (lane >> 4) * 8;
            ldsm4(af[mi][s], s2u(&sm.A[s][row][kh]));
        }
    const int r = lane >> 2;
    ulonglong2 I1[4], I2[4];                  /* q = mi*2+half */
#pragma unroll
    for (int q = 0; q < 4; q++) {
        int irow = wy * 32 + q * 8 + r;
        I1[q] = *(const ulonglong2*)&sm.X1i[irow][0];
        I2[q] = *(const ulonglong2*)&sm.X1i[irow][4];
    }

    float part = 0.f;

    for (int jt = 0; jt < JCHUNK; jt++) {
        JPack& jb = sm.jb[jt & 1];

        /* prefetch next j-tile into the other buffer (overlaps compute) */
        if (jt + 1 < JCHUNK) {
            const float4* gj = (const float4*)&g_jp[b][jbase + jt + 1];
            float4* sj = (float4*)&sm.jb[(jt + 1) & 1];
#pragma unroll
            for (int k = 0; k < 4; k++)
                cpa16(s2u(sj + tid + k * 256), gj + tid + k * 256);
            CPA_COMMIT();
        }

        /* ---- gramian: bf16 3-term split, np-outer to cap bfr liveness ---- */
        float acc[2][4][4];
#pragma unroll
        for (int mi = 0; mi < 2; mi++)
#pragma unroll
            for (int ni = 0; ni < 4; ni++)
#pragma unroll
                for (int k = 0; k < 4; k++) acc[mi][ni][k] = 0.f;

#pragma unroll
        for (int np = 0; np < 2; np++) {
            uint32_t bh[4], bl[4];
            {
                int row = wx * 32 + np * 16 + ((lane >> 4) & 1) * 8 + (lane & 7);
                int kh  = ((lane >> 3) & 1) * 8;
                ldsm4(bh, s2u(&jb.B[0][row][kh]));
                ldsm4(bl, s2u(&jb.B[1][row][kh]));
            }
#pragma unroll
            for (int mi = 0; mi < 2; mi++)
#pragma unroll
                for (int oo = 0; oo < 2; oo++) {
                    const int ni = np * 2 + oo, o = oo * 2;
                    mma_bf16(acc[mi][ni], af[mi][0], bh[o], bh[o + 1]);
                    mma_bf16(acc[mi][ni], af[mi][0], bl[o], bl[o + 1]);
                    mma_bf16(acc[mi][ni], af[mi][1], bh[o], bh[o + 1]);
                }
        }

        /* ---- RBF weights + combine ---- */
#pragma unroll
        for (int ni = 0; ni < 4; ni++) {
            const int jc = wx * 32 + ni * 8 + 2 * (lane & 3);
            u64 T0 = *(const u64*)&jb.JT[0][jc];
            u64 T1 = *(const u64*)&jb.JT[1][jc];
            u64 T2 = *(const u64*)&jb.JT[2][jc];
            u64 N0 = *(const u64*)&jb.JN[0][jc];
            u64 N1 = *(const u64*)&jb.JN[1][jc];
            u64 N2 = *(const u64*)&jb.JN[2][jc];
            u64 BT = *(const u64*)&jb.bt[jc];
            u64 BN = *(const u64*)&jb.bn[jc];
#pragma unroll
            for (int q = 0; q < 4; q++) {
                const int mi = q >> 1, half = q & 1;
                u64 st = add2(I2[q].y, BT);
                fma2(st, I1[q].x, T0); fma2(st, I1[q].y, T1); fma2(st, I2[q].x, T2);
                u64 sn = add2(I2[q].y, BN);
                fma2(sn, I1[q].x, N0); fma2(sn, I1[q].y, N1); fma2(sn, I2[q].x, N2);
                float2 s = unpk(st), n = unpk(sn);
                float w0 = fexp2(s.x) - fexp2(n.x);
                float w1 = fexp2(s.y) - fexp2(n.y);
                part = fmaf(w0, acc[mi][ni][half * 2],     part);
                part = fmaf(w1, acc[mi][ni][half * 2 + 1], part);
            }
        }

        /* ensure prefetch landed; release current buffer for next prefetch */
        CPA_WAIT0();
        __syncthreads();
    }

    /* ---- block reduce -> one double atomic ---- */
#pragma unroll
    for (int o = 16; o; o >>= 1) part += __shfl_down_sync(0xffffffffu, part, o);
    if (lane == 0) sm.warpsum[w] = part;
    __syncthreads();
    if (tid == 0) {
        float s = 0.f;
#pragma unroll
        for (int k = 0; k < 8; k++) s += sm.warpsum[k];
        atomicAdd(&g_S[b], (double)s);
    }
}

/* ------------------------- finalize (one warp) --------------------------- */
__global__ void fin_kernel(float* out) {
    const int lane = threadIdx.x;
    float fns = 0.f, s10 = 0.f, s20 = 0.f, s11 = 0.f, s21 = 0.f;
    for (int k = lane; k < PREPB; k += 32) {
        fns += g_part[0][k][0] + g_part[1][k][0];
        s10 += g_part[0][k][1];
        s20 += g_part[0][k][2];
        s11 += g_part[1][k][1];
        s21 += g_part[1][k][2];
    }
#pragma unroll
    for (int o = 16; o; o >>= 1) {
        fns += __shfl_down_sync(0xffffffffu, fns, o);
        s10 += __shfl_down_sync(0xffffffffu, s10, o);
        s20 += __shfl_down_sync(0xffffffffu, s20, o);
        s11 += __shfl_down_sync(0xffffffffu, s11, o);
        s21 += __shfl_down_sync(0xffffffffu, s21, o);
    }
    if (lane == 0) {
        double tot = g_S[0] / ((double)s10 * (double)s20)
                   + g_S[1] / ((double)s11 * (double)s21);
        float fl = (float)(-tot);
        out[0] = fl;
        out[1] = fl;
        out[2] = fns * 100.f;
    }
}

/* ------------------------- launch ---------------------------------------- */
extern "C" void kernel_launch(void* const* d_in, const int* in_sizes, int n_in,
                              void* d_out, int out_size) {
    const float* f1   = (const float*)d_in[0];
    const float* f2   = (const float*)d_in[1];
    const float* dp1  = (const float*)d_in[2];
    const float* dp2  = (const float*)d_in[3];
    const float* pose = (const float*)d_in[4];
    const float* yz1  = (const float*)d_in[7];
    float* out = (float*)d_out;

    prep_kernel<<<dim3(PREPB, BB), 256>>>(f1, f2, dp1, dp2, pose, yz1);
    pair_kernel<<<dim3(NJB, NT * 2, BB), 256>>>();
    fin_kernel<<<1, 32>>>(out);
}

// round 16
// speedup vs baseline: 1.0082x; 1.0082x over previous
#include <cuda_runtime.h>
#include <cuda_bf16.h>
#include <cstdint>

#define NPTS 6912
#define CF 16
#define BB 2
#define TILE 128
#define NT (NPTS / TILE)     /* 54 */
#define JCHUNK 6
#define NJB (NT / JCHUNK)    /* 9 */
#define PREPB (NPTS / 128)   /* 54 */
#define EPSF 1e-8f
#define NEG_SCALE (-14.426950408889634f)
#define POS2SCALE (28.853900817779268f)
#define ROWP 24              /* bf16/row: 16 used + 8 pad -> 48B stride */

typedef unsigned long long u64;

/* ------------------------- packed per-tile records ----------------------- */
struct APack {               /* 16384 B */
    __nv_bfloat16 A[2][TILE][ROWP];     /* hi/lo split, 12KB */
    float X1i[TILE][8];                 /* {Px,Px,Py,Py,Pz,Pz,as,as} 4KB */
};
struct JPack {               /* 16384 B */
    __nv_bfloat16 B[2][TILE][ROWP];     /* 12KB */
    float JT[3][TILE];
    float JN[3][TILE];
    float bt[TILE], bn[TILE];
};

__device__ APack g_ap[BB][NT];
__device__ JPack g_jp[BB][NT];
__device__ float  g_part[BB][PREPB][3];
__device__ double g_S[BB];

/* ------------------------- helpers -------------------------------------- */
__device__ __forceinline__ float2 unpk(u64 v) {
    float2 r; asm("mov.b64 {%0, %1}, %2;" : "=f"(r.x), "=f"(r.y) : "l"(v)); return r;
}
__device__ __forceinline__ void fma2(u64 &d, u64 a, u64 b) {
    asm("fma.rn.f32x2 %0, %1, %2, %0;" : "+l"(d) : "l"(a), "l"(b));
}
__device__ __forceinline__ u64 add2(u64 a, u64 b) {
    u64 r; asm("add.rn.f32x2 %0, %1, %2;" : "=l"(r) : "l"(a), "l"(b)); return r;
}
__device__ __forceinline__ float fexp2(float x) {
    float r; asm("ex2.approx.f32 %0, %1;" : "=f"(r) : "f"(x)); return r;
}
__device__ __forceinline__ uint32_t s2u(const void* p) {
    uint32_t a;
    asm("{ .reg .u64 t; cvta.to.shared.u64 t, %1; cvt.u32.u64 %0, t; }" : "=r"(a) : "l"(p));
    return a;
}
__device__ __forceinline__ void ldsm4(uint32_t r[4], uint32_t addr) {
    asm volatile("ldmatrix.sync.aligned.m8n8.x4.shared.b16 {%0,%1,%2,%3}, [%4];"
                 : "=r"(r[0]), "=r"(r[1]), "=r"(r[2]), "=r"(r[3]) : "r"(addr));
}
__device__ __forceinline__ void mma_bf16(float d[4], const uint32_t a[4],
                                         uint32_t b0, uint32_t b1) {
    asm volatile("mma.sync.aligned.m16n8k16.row.col.f32.bf16.bf16.f32 "
                 "{%0,%1,%2,%3}, {%4,%5,%6,%7}, {%8,%9}, {%0,%1,%2,%3};"
                 : "+f"(d[0]), "+f"(d[1]), "+f"(d[2]), "+f"(d[3])
                 : "r"(a[0]), "r"(a[1]), "r"(a[2]), "r"(a[3]), "r"(b0), "r"(b1));
}
__device__ __forceinline__ void cpa16(uint32_t dst, const void* src) {
    asm volatile("cp.async.cg.shared.global [%0], [%1], 16;" :: "r"(dst), "l"(src));
}
#define CPA_COMMIT() asm volatile("cp.async.commit_group;" ::: "memory")
#define CPA_WAIT0()  asm volatile("cp.async.wait_group 0;" ::: "memory")

/* ------------------------- prep (128-thr blocks) ------------------------- */
__global__ void prep_kernel(const float* __restrict__ f1, const float* __restrict__ f2,
                            const float* __restrict__ dp1, const float* __restrict__ dp2,
                            const float* __restrict__ pose, const float* __restrict__ yz1) {
    const int b = blockIdx.y;
    const int i = blockIdx.x * 128 + threadIdx.x;
    const int tile = i >> 7, row = i & 127;
    float fns, m1c, m2c;
    {
        float d1 = dp1[b * NPTS + i], d2 = dp2[b * NPTS + i];
        float m1 = (d1 > 0.f) ? 1.f : 0.f;
        float m2 = (d2 > 0.f) ? 1.f : 0.f;
        float v1[CF], v2[CF];
        float s1 = 0.f, s2 = 0.f;
#pragma unroll
        for (int c = 0; c < CF; c++) {
            v1[c] = f1[((size_t)b * CF + c) * NPTS + i];
            v2[c] = f2[((size_t)b * CF + c) * NPTS + i];
            s1 = fmaf(v1[c], v1[c], s1);
            s2 = fmaf(v2[c], v2[c], s2);
        }
        float n1 = sqrtf(s1), n2 = sqrtf(s2);
        float iv1 = m1 / (n1 + EPSF), iv2 = m2 / (n2 + EPSF);

        union { uint4 q[2]; __nv_bfloat162 h[8]; } AH, AL, BH, BL;
#pragma unroll
        for (int t = 0; t < 8; t++) {
            float a0 = v1[2 * t] * iv1,     a1 = v1[2 * t + 1] * iv1;
            __nv_bfloat16 h0 = __float2bfloat16(a0), h1 = __float2bfloat16(a1);
            AH.h[t].x = h0; AH.h[t].y = h1;
            AL.h[t].x = __float2bfloat16(a0 - __bfloat162float(h0));
            AL.h[t].y = __float2bfloat16(a1 - __bfloat162float(h1));
            float b0 = v2[2 * t] * iv2,     b1 = v2[2 * t + 1] * iv2;
            __nv_bfloat16 g0 = __float2bfloat16(b0), g1 = __float2bfloat16(b1);
            BH.h[t].x = g0; BH.h[t].y = g1;
            BL.h[t].x = __float2bfloat16(b0 - __bfloat162float(g0));
            BL.h[t].y = __float2bfloat16(b1 - __bfloat162float(g1));
        }
        APack& ap = g_ap[b][tile];
        JPack& jp = g_jp[b][tile];
        *(uint4*)&ap.A[0][row][0] = AH.q[0];
        *(uint4*)&ap.A[0][row][8] = AH.q[1];
        *(uint4*)&ap.A[1][row][0] = AL.q[0];
        *(uint4*)&ap.A[1][row][8] = AL.q[1];
        *(uint4*)&jp.B[0][row][0] = BH.q[0];
        *(uint4*)&jp.B[0][row][8] = BH.q[1];
        *(uint4*)&jp.B[1][row][0] = BL.q[0];
        *(uint4*)&jp.B[1][row][8] = BL.q[1];

        float y0 = yz1[i], y1 = yz1[NPTS + i], y2 = yz1[2 * NPTS + i];
        float ax = y0 * d1, ay = y1 * d1, az = y2 * d1;
        float as = NEG_SCALE * (ax * ax + ay * ay + az * az);
        *(float4*)&ap.X1i[row][0] = make_float4(POS2SCALE * ax, POS2SCALE * ax,
                                                POS2SCALE * ay, POS2SCALE * ay);
        *(float4*)&ap.X1i[row][4] = make_float4(POS2SCALE * az, POS2SCALE * az, as, as);

        float bx = y0 * d2, by = y1 * d2, bz = y2 * d2;
        jp.JN[0][row] = bx; jp.JN[1][row] = by; jp.JN[2][row] = bz;
        jp.bn[row] = NEG_SCALE * (bx * bx + by * by + bz * bz);
        const float* P = pose + b * 16;
        float tx = P[0] * bx + P[1] * by + P[2]  * bz + P[3];
        float ty = P[4] * bx + P[5] * by + P[6]  * bz + P[7];
        float tz = P[8] * bx + P[9] * by + P[10] * bz + P[11];
        jp.JT[0][row] = tx; jp.JT[1][row] = ty; jp.JT[2][row] = tz;
        jp.bt[row] = NEG_SCALE * (tx * tx + ty * ty + tz * tz);
        fns = n1 * m1 + n2 * m2; m1c = m1; m2c = m2;
    }
#pragma unroll
    for (int o = 16; o; o >>= 1) {
        fns += __shfl_down_sync(0xffffffffu, fns, o);
        m1c += __shfl_down_sync(0xffffffffu, m1c, o);
        m2c += __shfl_down_sync(0xffffffffu, m2c, o);
    }
    __shared__ float rf[4], r1[4], r2[4];
    int w = threadIdx.x >> 5, l = threadIdx.x & 31;
    if (l == 0) { rf[w] = fns; r1[w] = m1c; r2[w] = m2c; }
    __syncthreads();
    if (threadIdx.x == 0) {
        float a = 0.f, c1 = 0.f, c2 = 0.f;
#pragma unroll
        for (int k = 0; k < 4; k++) { a += rf[k]; c1 += r1[k]; c2 += r2[k]; }
        g_part[b][blockIdx.x][0] = a;
        g_part[b][blockIdx.x][1] = c1;
        g_part[b][blockIdx.x][2] = c2;
        if (blockIdx.x == 0) g_S[b] = 0.0;
    }
}

/* --------- pair: 64-row half-strip, 256 threads, 3 blocks/SM ------------ */
/* low-liveness body: per-np interleaved gram+RBF, I-geom reloaded from smem */
struct SmemT {
    __nv_bfloat16 A[2][64][ROWP];       /* 6KB (contig 384 float4) */
    float X1i[64][8];                   /* 2KB (contig 128 float4) */
    JPack jb[2];                        /* 32KB double buffer */
    float warpsum[8];
};

__global__ void __launch_bounds__(256, 3) pair_kernel() {
    __shared__ SmemT sm;
    const int b     = blockIdx.z;
    const int ti    = blockIdx.y >> 1;
    const int ihalf = blockIdx.y & 1;
    const int jbase = blockIdx.x * JCHUNK;
    const int tid = threadIdx.x;
    const int w = tid >> 5, lane = tid & 31;
    const int wy = w >> 2, wx = w & 3;       /* 2x4 warps of 32x32 slabs */

    /* prologue: async-fill A-half (3 contig chunks) + first J-pack */
    {
        const char* gA = (const char*)&g_ap[b][ti];
        float4* sa = (float4*)&sm;           /* A then X1i, contiguous 512 f4 */
#pragma unroll
        for (int k = 0; k < 2; k++) {
            int idx = tid + k * 256;
            const char* src;
            if (idx < 192)      src = gA + (size_t)ihalf * 3072 + (size_t)idx * 16;
            else if (idx < 384) src = gA + 6144 + (size_t)ihalf * 3072 + (size_t)(idx - 192) * 16;
            else                src = gA + 12288 + (size_t)ihalf * 2048 + (size_t)(idx - 384) * 16;
            cpa16(s2u(sa + idx), src);
        }
        const float4* gj = (const float4*)&g_jp[b][jbase];
        float4* sj = (float4*)&sm.jb[0];
#pragma unroll
        for (int k = 0; k < 4; k++)
            cpa16(s2u(sj + tid + k * 256), gj + tid + k * 256);
        CPA_COMMIT();
        CPA_WAIT0();
    }
    __syncthreads();

    /* A fragments: pinned in registers for the whole strip (16 regs) */
    uint32_t af[2][2][4];                     /* [mi][split][4] */
#pragma unroll
    for (int mi = 0; mi < 2; mi++)
#pragma unroll
        for (int s = 0; s < 2; s++) {
            int row = wy * 32 + mi * 16 + (lane & 15);
            int kh  = (lane >> 4) * 8;
            ldsm4(af[mi][s], s2u(&sm.A[s][row][kh]));
        }
    const int r = lane >> 2;

    float part = 0.f;

    for (int jt = 0; jt < JCHUNK; jt++) {
        JPack& jb = sm.jb[jt & 1];

        /* prefetch next j-tile into the other buffer (overlaps compute) */
        if (jt + 1 < JCHUNK) {
            const float4* gj = (const float4*)&g_jp[b][jbase + jt + 1];
            float4* sj = (float4*)&sm.jb[(jt + 1) & 1];
#pragma unroll
            for (int k = 0; k < 4; k++)
                cpa16(s2u(sj + tid + k * 256), gj + tid + k * 256);
            CPA_COMMIT();
        }

        /* ---- per-np: gram (12 HMMA) then immediately its RBF+combine ---- */
#pragma unroll
        for (int np = 0; np < 2; np++) {
            uint32_t bh[4], bl[4];
            {
                int row = wx * 32 + np * 16 + ((lane >> 4) & 1) * 8 + (lane & 7);
                int kh  = ((lane >> 3) & 1) * 8;
                ldsm4(bh, s2u(&jb.B[0][row][kh]));
                ldsm4(bl, s2u(&jb.B[1][row][kh]));
            }
            float acc[2][2][4];               /* [mi][oo][4] — dies per np */
#pragma unroll
            for (int mi = 0; mi < 2; mi++)
#pragma unroll
                for (int oo = 0; oo < 2; oo++) {
#pragma unroll
                    for (int k = 0; k < 4; k++) acc[mi][oo][k] = 0.f;
                    const int o = oo * 2;
                    mma_bf16(acc[mi][oo], af[mi][0], bh[o], bh[o + 1]);
                    mma_bf16(acc[mi][oo], af[mi][0], bl[o], bl[o + 1]);
                    mma_bf16(acc[mi][oo], af[mi][1], bh[o], bh[o + 1]);
                }

#pragma unroll
            for (int oo = 0; oo < 2; oo++) {
                const int ni = np * 2 + oo;
                const int jc = wx * 32 + ni * 8 + 2 * (lane & 3);
                u64 T0 = *(const u64*)&jb.JT[0][jc];
                u64 T1 = *(const u64*)&jb.JT[1][jc];
                u64 T2 = *(const u64*)&jb.JT[2][jc];
                u64 N0 = *(const u64*)&jb.JN[0][jc];
                u64 N1 = *(const u64*)&jb.JN[1][jc];
                u64 N2 = *(const u64*)&jb.JN[2][jc];
                u64 BT = *(const u64*)&jb.bt[jc];
                u64 BN = *(const u64*)&jb.bn[jc];
#pragma unroll
                for (int q = 0; q < 4; q++) {
                    const int mi = q >> 1, half = q & 1;
                    const int irow = wy * 32 + q * 8 + r;
                    ulonglong2 Ia = *(const ulonglong2*)&sm.X1i[irow][0];
                    ulonglong2 Ib = *(const ulonglong2*)&sm.X1i[irow][4];
                    u64 st = add2(Ib.y, BT);
                    fma2(st, Ia.x, T0); fma2(st, Ia.y, T1); fma2(st, Ib.x, T2);
                    u64 sn = add2(Ib.y, BN);
                    fma2(sn, Ia.x, N0); fma2(sn, Ia.y, N1); fma2(sn, Ib.x, N2);
                    float2 s = unpk(st), n = unpk(sn);
                    float w0 = fexp2(s.x) - fexp2(n.x);
                    float w1 = fexp2(s.y) - fexp2(n.y);
                    part = fmaf(w0, acc[mi][oo][half * 2],     part);
                    part = fmaf(w1, acc[mi][oo][half * 2 + 1], part);
                }
            }
        }

        /* ensure prefetch landed; release current buffer for next prefetch */
        CPA_WAIT0();
        __syncthreads();
    }

    /* ---- block reduce -> one double atomic ---- */
#pragma unroll
    for (int o = 16; o; o >>= 1) part += __shfl_down_sync(0xffffffffu, part, o);
    if (lane == 0) sm.warpsum[w] = part;
    __syncthreads();
    if (tid == 0) {
        float s = 0.f;
#pragma unroll
        for (int k = 0; k < 8; k++) s += sm.warpsum[k];
        atomicAdd(&g_S[b], (double)s);
    }
}

/* ------------------------- finalize (one warp) --------------------------- */
__global__ void fin_kernel(float* out) {
    const int lane = threadIdx.x;
    float fns = 0.f, s10 = 0.f, s20 = 0.f, s11 = 0.f, s21 = 0.f;
    for (int k = lane; k < PREPB; k += 32) {
        fns += g_part[0][k][0] + g_part[1][k][0];
        s10 += g_part[0][k][1];
        s20 += g_part[0][k][2];
        s11 += g_part[1][k][1];
        s21 += g_part[1][k][2];
    }
#pragma unroll
    for (int o = 16; o; o >>= 1) {
        fns += __shfl_down_sync(0xffffffffu, fns, o);
        s10 += __shfl_down_sync(0xffffffffu, s10, o);
        s20 += __shfl_down_sync(0xffffffffu, s20, o);
        s11 += __shfl_down_sync(0xffffffffu, s11, o);
        s21 += __shfl_down_sync(0xffffffffu, s21, o);
    }
    if (lane == 0) {
        double tot = g_S[0] / ((double)s10 * (double)s20)
                   + g_S[1] / ((double)s11 * (double)s21);
        float fl = (float)(-tot);
        out[0] = fl;
        out[1] = fl;
        out[2] = fns * 100.f;
    }
}

/* ------------------------- launch ---------------------------------------- */
extern "C" void kernel_launch(void* const* d_in, const int* in_sizes, int n_in,
                              void* d_out, int out_size) {
    const float* f1   = (const float*)d_in[0];
    const float* f2   = (const float*)d_in[1];
    const float* dp1  = (const float*)d_in[2];
    const float* dp2  = (const float*)d_in[3];
    const float* pose = (const float*)d_in[4];
    const float* yz1  = (const float*)d_in[7];
    float* out = (float*)d_out;

    prep_kernel<<<dim3(PREPB, BB), 128>>>(f1, f2, dp1, dp2, pose, yz1);
    pair_kernel<<<dim3(NJB, NT * 2, BB), 256>>>();
    fin_kernel<<<1, 32>>>(out);
}